// round 2
// baseline (speedup 1.0000x reference)
#include <cuda_runtime.h>
#include <cuda_bf16.h>
#include <stdint.h>

#define N_NODES  50000
#define N_EDGES  800000
#define F        128
#define N_GRAPHS 128
#define N_CLASSES 10

// ---------------- scratch (no allocations allowed) ----------------
__device__ __align__(16) float g_H[N_NODES * F];     // GEMM output (messages source)
__device__ __align__(16) float g_ACC[N_NODES * F];   // aggregated layer output
__device__ float g_deg[N_NODES];
__device__ float g_dinv[N_NODES];
__device__ __align__(16) float g_gsum[N_GRAPHS * F];
__device__ float g_gcnt[N_GRAPHS];

// vectorized fp32 reduction (no return) — sm_90+
__device__ __forceinline__ void red_add_v4(float* p, float4 v) {
    asm volatile("red.relaxed.gpu.global.add.v4.f32 [%0], {%1, %2, %3, %4};"
                 :: "l"(p), "f"(v.x), "f"(v.y), "f"(v.z), "f"(v.w)
                 : "memory");
}

// ---------------- precompute: degrees / norm ----------------
__global__ void k_init() {
    int i = blockIdx.x * blockDim.x + threadIdx.x;
    if (i < N_NODES) g_deg[i] = 1.0f;            // self-loop contribution
    if (i < N_GRAPHS * F) g_gsum[i] = 0.0f;
    if (i < N_GRAPHS) g_gcnt[i] = 0.0f;
}

__global__ void k_deg(const int* __restrict__ ei) {
    int e = blockIdx.x * blockDim.x + threadIdx.x;
    if (e < N_EDGES) {
        int d = ei[N_EDGES + e];                  // dst row
        atomicAdd(&g_deg[d], 1.0f);
    }
}

__global__ void k_dinv() {
    int i = blockIdx.x * blockDim.x + threadIdx.x;
    if (i < N_NODES) g_dinv[i] = rsqrtf(g_deg[i]);   // deg >= 1 always
}

// ---------------- GEMM: H = act(X) @ W ; ACC = H*dinv^2 + b ----------------
// MODE 0: read Xin (no relu). MODE 1: read relu(g_ACC).
// Block: 64 rows x 128 cols, 256 threads, full K=128 in smem.
template <int MODE>
__global__ void __launch_bounds__(256, 2)
k_gemm(const float* __restrict__ Xin, const float* __restrict__ W,
       const float* __restrict__ bias) {
    extern __shared__ float smem[];
    float* sW = smem;            // 128*128 floats
    float* sX = smem + F * F;    // 64*128 floats

    const int tid  = threadIdx.x;
    const int row0 = blockIdx.x * 64;

    // load W (16384 floats = 4096 float4)
    #pragma unroll
    for (int i = 0; i < 16; i++)
        ((float4*)sW)[tid + i * 256] = ((const float4*)W)[tid + i * 256];

    // load X tile (8192 floats = 2048 float4), relu if MODE==1
    const float* src = (MODE == 0) ? Xin : g_ACC;
    #pragma unroll
    for (int i = 0; i < 8; i++) {
        int idx = tid + i * 256;        // float4 index
        int r   = idx >> 5;             // 32 float4 per row
        int gr  = row0 + r;
        float4 v = make_float4(0.f, 0.f, 0.f, 0.f);
        if (gr < N_NODES) {
            v = ((const float4*)(src + (size_t)gr * F))[idx & 31];
            if (MODE == 1) {
                v.x = fmaxf(v.x, 0.f); v.y = fmaxf(v.y, 0.f);
                v.z = fmaxf(v.z, 0.f); v.w = fmaxf(v.w, 0.f);
            }
        }
        ((float4*)sX)[idx] = v;
    }
    __syncthreads();

    const int rg = tid >> 5;     // 0..7  (row group of 8)
    const int cg = tid & 31;     // 0..31 (4 cols each)

    float4 acc[8];
    #pragma unroll
    for (int i = 0; i < 8; i++) acc[i] = make_float4(0.f, 0.f, 0.f, 0.f);

    #pragma unroll 4
    for (int k = 0; k < F; k += 4) {
        float4 w0 = *(float4*)&sW[(k + 0) * F + cg * 4];
        float4 w1 = *(float4*)&sW[(k + 1) * F + cg * 4];
        float4 w2 = *(float4*)&sW[(k + 2) * F + cg * 4];
        float4 w3 = *(float4*)&sW[(k + 3) * F + cg * 4];
        #pragma unroll
        for (int i = 0; i < 8; i++) {
            float4 xv = *(float4*)&sX[(rg * 8 + i) * F + k];
            acc[i].x += xv.x * w0.x + xv.y * w1.x + xv.z * w2.x + xv.w * w3.x;
            acc[i].y += xv.x * w0.y + xv.y * w1.y + xv.z * w2.y + xv.w * w3.y;
            acc[i].z += xv.x * w0.z + xv.y * w1.z + xv.z * w2.z + xv.w * w3.z;
            acc[i].w += xv.x * w0.w + xv.y * w1.w + xv.z * w2.w + xv.w * w3.w;
        }
    }

    float4 bv = *(const float4*)&bias[cg * 4];
    #pragma unroll
    for (int i = 0; i < 8; i++) {
        int r = row0 + rg * 8 + i;
        if (r < N_NODES) {
            float4 a = acc[i];
            *(float4*)&g_H[(size_t)r * F + cg * 4] = a;
            float di = g_dinv[r];
            float n  = di * di;                  // self-loop norm
            float4 o = make_float4(a.x * n + bv.x, a.y * n + bv.y,
                                   a.z * n + bv.z, a.w * n + bv.w);
            *(float4*)&g_ACC[(size_t)r * F + cg * 4] = o;
        }
    }
}

// ---------------- edge scatter: ACC[dst] += H[src] * dinv[src]*dinv[dst] ----------------
__global__ void k_scatter(const int* __restrict__ ei) {
    int w    = (blockIdx.x * blockDim.x + threadIdx.x) >> 5;
    int lane = threadIdx.x & 31;
    if (w >= N_EDGES) return;
    int s = __ldg(&ei[w]);
    int d = __ldg(&ei[N_EDGES + w]);
    float norm = __ldg(&g_dinv[s]) * __ldg(&g_dinv[d]);
    float4 v = *(const float4*)&g_H[(size_t)s * F + lane * 4];
    v.x *= norm; v.y *= norm; v.z *= norm; v.w *= norm;
    red_add_v4(&g_ACC[(size_t)d * F + lane * 4], v);
}

// ---------------- mean pool (sums + counts) ----------------
__global__ void k_pool(const int* __restrict__ batch) {
    int w    = (blockIdx.x * blockDim.x + threadIdx.x) >> 5;
    int lane = threadIdx.x & 31;
    if (w >= N_NODES) return;
    int g = __ldg(&batch[w]);
    float4 v = *(const float4*)&g_ACC[(size_t)w * F + lane * 4];
    red_add_v4(&g_gsum[g * F + lane * 4], v);
    if (lane == 0) atomicAdd(&g_gcnt[g], 1.0f);
}

// ---------------- head: out = (gsum/cnt) @ lin_w + lin_b ----------------
__global__ void k_final(const float* __restrict__ lin_w,
                        const float* __restrict__ lin_b,
                        float* __restrict__ out) {
    int g = blockIdx.x;
    int c = threadIdx.x;
    if (c >= N_CLASSES) return;
    float cnt = fmaxf(g_gcnt[g], 1.0f);
    float acc = 0.f;
    #pragma unroll 8
    for (int f = 0; f < F; f++)
        acc += g_gsum[g * F + f] * __ldg(&lin_w[f * N_CLASSES + c]);
    out[g * N_CLASSES + c] = acc / cnt + lin_b[c];
}

// ---------------- host ----------------
extern "C" void kernel_launch(void* const* d_in, const int* in_sizes, int n_in,
                              void* d_out, int out_size) {
    const float* x     = (const float*)d_in[0];
    const int*   ei    = (const int*)d_in[1];
    const int*   batch = (const int*)d_in[2];
    const float* w1 = (const float*)d_in[3];
    const float* b1 = (const float*)d_in[4];
    const float* w2 = (const float*)d_in[5];
    const float* b2 = (const float*)d_in[6];
    const float* w3 = (const float*)d_in[7];
    const float* b3 = (const float*)d_in[8];
    const float* lw = (const float*)d_in[9];
    const float* lb = (const float*)d_in[10];
    float* out = (float*)d_out;

    const int SMEM = (F * F + 64 * F) * (int)sizeof(float);   // 96 KB
    cudaFuncSetAttribute(k_gemm<0>, cudaFuncAttributeMaxDynamicSharedMemorySize, SMEM);
    cudaFuncSetAttribute(k_gemm<1>, cudaFuncAttributeMaxDynamicSharedMemorySize, SMEM);

    const int GB = (N_NODES + 63) / 64;                 // gemm blocks
    const int EB = (N_EDGES + 7) / 8;                   // scatter blocks (8 warps/blk)
    const int PB = (N_NODES + 7) / 8;                   // pool blocks

    k_init<<<(N_NODES + 255) / 256, 256>>>();
    k_deg<<<(N_EDGES + 255) / 256, 256>>>(ei);
    k_dinv<<<(N_NODES + 255) / 256, 256>>>();

    // layer 1
    k_gemm<0><<<GB, 256, SMEM>>>(x, w1, b1);
    k_scatter<<<EB, 256>>>(ei);
    // layer 2 (relu on input)
    k_gemm<1><<<GB, 256, SMEM>>>(x, w2, b2);
    k_scatter<<<EB, 256>>>(ei);
    // layer 3 (relu on input, no relu on output)
    k_gemm<1><<<GB, 256, SMEM>>>(x, w3, b3);
    k_scatter<<<EB, 256>>>(ei);

    // mean pool + head
    k_pool<<<PB, 256>>>(batch);
    k_final<<<N_GRAPHS, 32>>>(lw, lb, out);
}

// round 3
// speedup vs baseline: 1.1728x; 1.1728x over previous
#include <cuda_runtime.h>
#include <cuda_bf16.h>
#include <stdint.h>

#define N_NODES  50000
#define N_EDGES  800000
#define F        128
#define N_GRAPHS 128
#define N_CLASSES 10

// ---------------- scratch (no allocations allowed) ----------------
__device__ __align__(16) float g_H[N_NODES * F];     // GEMM output
__device__ __align__(16) float g_ACC[N_NODES * F];   // aggregated layer output
__device__ float g_dinv[N_NODES];
__device__ int   g_degi[N_NODES];
__device__ int   g_rowptr[N_NODES + 1];
__device__ int   g_cursor[N_NODES];
__device__ int   g_csrc[N_EDGES];
__device__ float g_cnorm[N_EDGES];
__device__ __align__(16) float g_gsum[N_GRAPHS * F];
__device__ float g_gcnt[N_GRAPHS];

__device__ __forceinline__ void red_add_v4(float* p, float4 v) {
    asm volatile("red.relaxed.gpu.global.add.v4.f32 [%0], {%1, %2, %3, %4};"
                 :: "l"(p), "f"(v.x), "f"(v.y), "f"(v.z), "f"(v.w)
                 : "memory");
}

// ---------------- precompute ----------------
__global__ void k_init() {
    int i = blockIdx.x * blockDim.x + threadIdx.x;
    if (i < N_NODES) g_degi[i] = 0;
    if (i < N_GRAPHS * F) g_gsum[i] = 0.0f;
    if (i < N_GRAPHS) g_gcnt[i] = 0.0f;
}

__global__ void k_deg(const int* __restrict__ ei) {
    int e = blockIdx.x * blockDim.x + threadIdx.x;
    if (e < N_EDGES) atomicAdd(&g_degi[ei[N_EDGES + e]], 1);
}

__global__ void k_dinv() {
    int i = blockIdx.x * blockDim.x + threadIdx.x;
    if (i < N_NODES) g_dinv[i] = rsqrtf((float)g_degi[i] + 1.0f);  // +1 self-loop
}

// single-block exclusive scan of g_degi -> g_rowptr (+ cursor copy)
__global__ void k_scan() {
    __shared__ int s[1024];
    const int tid = threadIdx.x;
    const int CH = (N_NODES + 1023) / 1024;          // 49
    int start = tid * CH;
    int end   = min(start + CH, N_NODES);
    int sum = 0;
    for (int i = start; i < end; i++) sum += g_degi[i];
    s[tid] = sum;
    __syncthreads();
    // Kogge-Stone inclusive scan
    for (int off = 1; off < 1024; off <<= 1) {
        int t = 0;
        if (tid >= off) t = s[tid - off];
        __syncthreads();
        if (tid >= off) s[tid] += t;
        __syncthreads();
    }
    int run = s[tid] - sum;                          // exclusive prefix of this chunk
    for (int i = start; i < end; i++) {
        g_rowptr[i] = run;
        g_cursor[i] = run;
        run += g_degi[i];
    }
    if (tid == 1023) g_rowptr[N_NODES] = N_EDGES;
}

__global__ void k_fill(const int* __restrict__ ei) {
    int e = blockIdx.x * blockDim.x + threadIdx.x;
    if (e < N_EDGES) {
        int s = ei[e];
        int d = ei[N_EDGES + e];
        int pos = atomicAdd(&g_cursor[d], 1);
        g_csrc[pos]  = s;
        g_cnorm[pos] = g_dinv[s] * g_dinv[d];
    }
}

// ---------------- GEMM: H = act(X) @ W ----------------
// MODE 0: read Xin (no relu). MODE 1: read relu(g_ACC).
template <int MODE>
__global__ void __launch_bounds__(256, 2)
k_gemm(const float* __restrict__ Xin, const float* __restrict__ W) {
    extern __shared__ float smem[];
    float* sW = smem;            // 128*128
    float* sX = smem + F * F;    // 64*128

    const int tid  = threadIdx.x;
    const int row0 = blockIdx.x * 64;

    #pragma unroll
    for (int i = 0; i < 16; i++)
        ((float4*)sW)[tid + i * 256] = ((const float4*)W)[tid + i * 256];

    const float* src = (MODE == 0) ? Xin : g_ACC;
    #pragma unroll
    for (int i = 0; i < 8; i++) {
        int idx = tid + i * 256;
        int r   = idx >> 5;
        int gr  = row0 + r;
        float4 v = make_float4(0.f, 0.f, 0.f, 0.f);
        if (gr < N_NODES) {
            v = ((const float4*)(src + (size_t)gr * F))[idx & 31];
            if (MODE == 1) {
                v.x = fmaxf(v.x, 0.f); v.y = fmaxf(v.y, 0.f);
                v.z = fmaxf(v.z, 0.f); v.w = fmaxf(v.w, 0.f);
            }
        }
        ((float4*)sX)[idx] = v;
    }
    __syncthreads();

    const int rg = tid >> 5;
    const int cg = tid & 31;

    float4 acc[8];
    #pragma unroll
    for (int i = 0; i < 8; i++) acc[i] = make_float4(0.f, 0.f, 0.f, 0.f);

    #pragma unroll 4
    for (int k = 0; k < F; k += 4) {
        float4 w0 = *(float4*)&sW[(k + 0) * F + cg * 4];
        float4 w1 = *(float4*)&sW[(k + 1) * F + cg * 4];
        float4 w2 = *(float4*)&sW[(k + 2) * F + cg * 4];
        float4 w3 = *(float4*)&sW[(k + 3) * F + cg * 4];
        #pragma unroll
        for (int i = 0; i < 8; i++) {
            float4 xv = *(float4*)&sX[(rg * 8 + i) * F + k];
            acc[i].x += xv.x * w0.x + xv.y * w1.x + xv.z * w2.x + xv.w * w3.x;
            acc[i].y += xv.x * w0.y + xv.y * w1.y + xv.z * w2.y + xv.w * w3.y;
            acc[i].z += xv.x * w0.z + xv.y * w1.z + xv.z * w2.z + xv.w * w3.z;
            acc[i].w += xv.x * w0.w + xv.y * w1.w + xv.z * w2.w + xv.w * w3.w;
        }
    }

    #pragma unroll
    for (int i = 0; i < 8; i++) {
        int r = row0 + rg * 8 + i;
        if (r < N_NODES)
            *(float4*)&g_H[(size_t)r * F + cg * 4] = acc[i];
    }
}

// ---------------- aggregate: ACC[d] = sum_in norm*H[s] + dinv[d]^2*H[d] + b ----------------
__global__ void __launch_bounds__(256)
k_aggregate(const float* __restrict__ bias) {
    const int warp = (blockIdx.x * blockDim.x + threadIdx.x) >> 5;
    const int lane = threadIdx.x & 31;
    if (warp >= N_NODES) return;
    const int d = warp;

    const int beg = __ldg(&g_rowptr[d]);
    const int end = __ldg(&g_rowptr[d + 1]);
    const float di = __ldg(&g_dinv[d]);

    // self-loop
    float4 acc = *(const float4*)&g_H[(size_t)d * F + lane * 4];
    float sn = di * di;
    acc.x *= sn; acc.y *= sn; acc.z *= sn; acc.w *= sn;

    int j = beg;
    // 2-deep software pipeline on the gather
    if (j < end) {
        int   s0 = __ldg(&g_csrc[j]);
        float n0 = __ldg(&g_cnorm[j]);
        float4 v0 = *(const float4*)&g_H[(size_t)s0 * F + lane * 4];
        for (j = beg + 1; j < end; j++) {
            int   s1 = __ldg(&g_csrc[j]);
            float n1 = __ldg(&g_cnorm[j]);
            float4 v1 = *(const float4*)&g_H[(size_t)s1 * F + lane * 4];
            acc.x += n0 * v0.x; acc.y += n0 * v0.y;
            acc.z += n0 * v0.z; acc.w += n0 * v0.w;
            v0 = v1; n0 = n1;
        }
        acc.x += n0 * v0.x; acc.y += n0 * v0.y;
        acc.z += n0 * v0.z; acc.w += n0 * v0.w;
    }

    float4 bv = *(const float4*)&bias[lane * 4];
    acc.x += bv.x; acc.y += bv.y; acc.z += bv.z; acc.w += bv.w;
    *(float4*)&g_ACC[(size_t)d * F + lane * 4] = acc;
}

// ---------------- mean pool ----------------
__global__ void k_pool(const int* __restrict__ batch) {
    int w    = (blockIdx.x * blockDim.x + threadIdx.x) >> 5;
    int lane = threadIdx.x & 31;
    if (w >= N_NODES) return;
    int g = __ldg(&batch[w]);
    float4 v = *(const float4*)&g_ACC[(size_t)w * F + lane * 4];
    red_add_v4(&g_gsum[g * F + lane * 4], v);
    if (lane == 0) atomicAdd(&g_gcnt[g], 1.0f);
}

// ---------------- head ----------------
__global__ void k_final(const float* __restrict__ lin_w,
                        const float* __restrict__ lin_b,
                        float* __restrict__ out) {
    int g = blockIdx.x;
    int c = threadIdx.x;
    if (c >= N_CLASSES) return;
    float cnt = fmaxf(g_gcnt[g], 1.0f);
    float acc = 0.f;
    #pragma unroll 8
    for (int f = 0; f < F; f++)
        acc += g_gsum[g * F + f] * __ldg(&lin_w[f * N_CLASSES + c]);
    out[g * N_CLASSES + c] = acc / cnt + lin_b[c];
}

// ---------------- host ----------------
extern "C" void kernel_launch(void* const* d_in, const int* in_sizes, int n_in,
                              void* d_out, int out_size) {
    const float* x     = (const float*)d_in[0];
    const int*   ei    = (const int*)d_in[1];
    const int*   batch = (const int*)d_in[2];
    const float* w1 = (const float*)d_in[3];
    const float* b1 = (const float*)d_in[4];
    const float* w2 = (const float*)d_in[5];
    const float* b2 = (const float*)d_in[6];
    const float* w3 = (const float*)d_in[7];
    const float* b3 = (const float*)d_in[8];
    const float* lw = (const float*)d_in[9];
    const float* lb = (const float*)d_in[10];
    float* out = (float*)d_out;

    const int SMEM = (F * F + 64 * F) * (int)sizeof(float);   // 96 KB
    cudaFuncSetAttribute(k_gemm<0>, cudaFuncAttributeMaxDynamicSharedMemorySize, SMEM);
    cudaFuncSetAttribute(k_gemm<1>, cudaFuncAttributeMaxDynamicSharedMemorySize, SMEM);

    const int GB = (N_NODES + 63) / 64;
    const int AB = (N_NODES + 7) / 8;     // aggregate: 8 warps/block
    const int PB = (N_NODES + 7) / 8;

    k_init<<<(N_NODES + 255) / 256, 256>>>();
    k_deg<<<(N_EDGES + 255) / 256, 256>>>(ei);
    k_dinv<<<(N_NODES + 255) / 256, 256>>>();
    k_scan<<<1, 1024>>>();
    k_fill<<<(N_EDGES + 255) / 256, 256>>>(ei);

    k_gemm<0><<<GB, 256, SMEM>>>(x, w1);
    k_aggregate<<<AB, 256>>>(b1);
    k_gemm<1><<<GB, 256, SMEM>>>(x, w2);
    k_aggregate<<<AB, 256>>>(b2);
    k_gemm<1><<<GB, 256, SMEM>>>(x, w3);
    k_aggregate<<<AB, 256>>>(b3);

    k_pool<<<PB, 256>>>(batch);
    k_final<<<N_GRAPHS, 32>>>(lw, lb, out);
}

// round 4
// speedup vs baseline: 1.5244x; 1.2998x over previous
#include <cuda_runtime.h>
#include <cuda_bf16.h>
#include <stdint.h>

#define N_NODES  50000
#define N_EDGES  800000
#define F        128
#define N_GRAPHS 128
#define N_CLASSES 10

// ---------------- scratch (no allocations allowed) ----------------
__device__ __align__(16) float g_H[N_NODES * F];     // GEMM output
__device__ __align__(16) float g_ACC[N_NODES * F];   // aggregated layer output
__device__ float g_dinv[N_NODES];
__device__ int   g_degi[N_NODES];
__device__ int   g_rowbeg[N_NODES];
__device__ int   g_cursor[N_NODES];
__device__ int   g_alloc;
__device__ int   g_csrc[N_EDGES];
__device__ float g_cnorm[N_EDGES];
__device__ __align__(16) float g_gsum[N_GRAPHS * F];
__device__ float g_gcnt[N_GRAPHS];

__device__ __forceinline__ void red_add_v4(float* p, float4 v) {
    asm volatile("red.relaxed.gpu.global.add.v4.f32 [%0], {%1, %2, %3, %4};"
                 :: "l"(p), "f"(v.x), "f"(v.y), "f"(v.z), "f"(v.w)
                 : "memory");
}

// ---------------- precompute ----------------
__global__ void k_init(const int* __restrict__ batch) {
    int i = blockIdx.x * blockDim.x + threadIdx.x;
    if (i < N_NODES) {
        g_degi[i] = 0;
        atomicAdd(&g_gcnt[batch[i]], 1.0f);   // gcnt zeroed below first
    }
    if (i < N_GRAPHS * F) g_gsum[i] = 0.0f;
    if (i == 0) g_alloc = 0;
}

// gcnt must be zeroed before k_init accumulates; separate tiny kernel first
__global__ void k_zero_cnt() {
    int i = threadIdx.x;
    if (i < N_GRAPHS) g_gcnt[i] = 0.0f;
}

__global__ void k_deg(const int* __restrict__ ei) {
    int e = blockIdx.x * blockDim.x + threadIdx.x;
    if (e < N_EDGES) atomicAdd(&g_degi[ei[N_EDGES + e]], 1);
}

// dinv + contiguous-segment allocation (order-free, no scan needed)
__global__ void k_alloc_seg() {
    int i = blockIdx.x * blockDim.x + threadIdx.x;
    if (i < N_NODES) {
        int deg = g_degi[i];
        g_dinv[i] = rsqrtf((float)deg + 1.0f);    // +1 self-loop
        int pos = atomicAdd(&g_alloc, deg);
        g_rowbeg[i] = pos;
        g_cursor[i] = pos;
    }
}

__global__ void k_fill(const int* __restrict__ ei) {
    int e = blockIdx.x * blockDim.x + threadIdx.x;
    if (e < N_EDGES) {
        int s = ei[e];
        int d = ei[N_EDGES + e];
        int pos = atomicAdd(&g_cursor[d], 1);
        g_csrc[pos]  = s;
        g_cnorm[pos] = g_dinv[s] * g_dinv[d];
    }
}

// ---------------- GEMM: H = act(X) @ W ----------------
// MODE 0: read Xin (no relu). MODE 1: read relu(g_ACC).
template <int MODE>
__global__ void __launch_bounds__(256, 2)
k_gemm(const float* __restrict__ Xin, const float* __restrict__ W) {
    extern __shared__ float smem[];
    float* sW = smem;            // 128*128
    float* sX = smem + F * F;    // 64*128

    const int tid  = threadIdx.x;
    const int row0 = blockIdx.x * 64;

    #pragma unroll
    for (int i = 0; i < 16; i++)
        ((float4*)sW)[tid + i * 256] = ((const float4*)W)[tid + i * 256];

    const float* src = (MODE == 0) ? Xin : g_ACC;
    #pragma unroll
    for (int i = 0; i < 8; i++) {
        int idx = tid + i * 256;
        int r   = idx >> 5;
        int gr  = row0 + r;
        float4 v = make_float4(0.f, 0.f, 0.f, 0.f);
        if (gr < N_NODES) {
            v = ((const float4*)(src + (size_t)gr * F))[idx & 31];
            if (MODE == 1) {
                v.x = fmaxf(v.x, 0.f); v.y = fmaxf(v.y, 0.f);
                v.z = fmaxf(v.z, 0.f); v.w = fmaxf(v.w, 0.f);
            }
        }
        ((float4*)sX)[idx] = v;
    }
    __syncthreads();

    const int rg = tid >> 5;
    const int cg = tid & 31;

    float4 acc[8];
    #pragma unroll
    for (int i = 0; i < 8; i++) acc[i] = make_float4(0.f, 0.f, 0.f, 0.f);

    #pragma unroll 4
    for (int k = 0; k < F; k += 4) {
        float4 w0 = *(float4*)&sW[(k + 0) * F + cg * 4];
        float4 w1 = *(float4*)&sW[(k + 1) * F + cg * 4];
        float4 w2 = *(float4*)&sW[(k + 2) * F + cg * 4];
        float4 w3 = *(float4*)&sW[(k + 3) * F + cg * 4];
        #pragma unroll
        for (int i = 0; i < 8; i++) {
            float4 xv = *(float4*)&sX[(rg * 8 + i) * F + k];
            acc[i].x += xv.x * w0.x + xv.y * w1.x + xv.z * w2.x + xv.w * w3.x;
            acc[i].y += xv.x * w0.y + xv.y * w1.y + xv.z * w2.y + xv.w * w3.y;
            acc[i].z += xv.x * w0.z + xv.y * w1.z + xv.z * w2.z + xv.w * w3.z;
            acc[i].w += xv.x * w0.w + xv.y * w1.w + xv.z * w2.w + xv.w * w3.w;
        }
    }

    #pragma unroll
    for (int i = 0; i < 8; i++) {
        int r = row0 + rg * 8 + i;
        if (r < N_NODES)
            *(float4*)&g_H[(size_t)r * F + cg * 4] = acc[i];
    }
}

// ---------------- aggregate: ACC[d] = sum_in norm*H[s] + dinv[d]^2*H[d] + b ----
// POOL=1: instead of storing ACC, RED the result into g_gsum[batch[d]].
template <int POOL>
__global__ void __launch_bounds__(256)
k_aggregate(const float* __restrict__ bias, const int* __restrict__ batch) {
    const int warp = (blockIdx.x * blockDim.x + threadIdx.x) >> 5;
    const int lane = threadIdx.x & 31;
    if (warp >= N_NODES) return;
    const int d = warp;

    const int beg = __ldg(&g_rowbeg[d]);
    const int end = beg + __ldg(&g_degi[d]);
    const float di = __ldg(&g_dinv[d]);

    // self-loop
    float4 acc = *(const float4*)&g_H[(size_t)d * F + lane * 4];
    float sn = di * di;
    acc.x *= sn; acc.y *= sn; acc.z *= sn; acc.w *= sn;

    int j = beg;
    if (j < end) {
        int   s0 = __ldg(&g_csrc[j]);
        float n0 = __ldg(&g_cnorm[j]);
        float4 v0 = *(const float4*)&g_H[(size_t)s0 * F + lane * 4];
        for (j = beg + 1; j < end; j++) {
            int   s1 = __ldg(&g_csrc[j]);
            float n1 = __ldg(&g_cnorm[j]);
            float4 v1 = *(const float4*)&g_H[(size_t)s1 * F + lane * 4];
            acc.x += n0 * v0.x; acc.y += n0 * v0.y;
            acc.z += n0 * v0.z; acc.w += n0 * v0.w;
            v0 = v1; n0 = n1;
        }
        acc.x += n0 * v0.x; acc.y += n0 * v0.y;
        acc.z += n0 * v0.z; acc.w += n0 * v0.w;
    }

    float4 bv = *(const float4*)&bias[lane * 4];
    acc.x += bv.x; acc.y += bv.y; acc.z += bv.z; acc.w += bv.w;

    if (POOL) {
        int g = __ldg(&batch[d]);
        red_add_v4(&g_gsum[g * F + lane * 4], acc);
    } else {
        *(float4*)&g_ACC[(size_t)d * F + lane * 4] = acc;
    }
}

// ---------------- head ----------------
__global__ void k_final(const float* __restrict__ lin_w,
                        const float* __restrict__ lin_b,
                        float* __restrict__ out) {
    int g = blockIdx.x;
    int c = threadIdx.x;
    if (c >= N_CLASSES) return;
    float cnt = fmaxf(g_gcnt[g], 1.0f);
    float acc = 0.f;
    #pragma unroll 8
    for (int f = 0; f < F; f++)
        acc += g_gsum[g * F + f] * __ldg(&lin_w[f * N_CLASSES + c]);
    out[g * N_CLASSES + c] = acc / cnt + lin_b[c];
}

// ---------------- host ----------------
extern "C" void kernel_launch(void* const* d_in, const int* in_sizes, int n_in,
                              void* d_out, int out_size) {
    const float* x     = (const float*)d_in[0];
    const int*   ei    = (const int*)d_in[1];
    const int*   batch = (const int*)d_in[2];
    const float* w1 = (const float*)d_in[3];
    const float* b1 = (const float*)d_in[4];
    const float* w2 = (const float*)d_in[5];
    const float* b2 = (const float*)d_in[6];
    const float* w3 = (const float*)d_in[7];
    const float* b3 = (const float*)d_in[8];
    const float* lw = (const float*)d_in[9];
    const float* lb = (const float*)d_in[10];
    float* out = (float*)d_out;

    const int SMEM = (F * F + 64 * F) * (int)sizeof(float);   // 96 KB
    cudaFuncSetAttribute(k_gemm<0>, cudaFuncAttributeMaxDynamicSharedMemorySize, SMEM);
    cudaFuncSetAttribute(k_gemm<1>, cudaFuncAttributeMaxDynamicSharedMemorySize, SMEM);

    const int GB = (N_NODES + 63) / 64;
    const int AB = (N_NODES + 7) / 8;     // aggregate: 8 warps/block

    k_zero_cnt<<<1, N_GRAPHS>>>();
    k_init<<<(N_NODES + 255) / 256, 256>>>(batch);
    k_deg<<<(N_EDGES + 255) / 256, 256>>>(ei);
    k_alloc_seg<<<(N_NODES + 255) / 256, 256>>>();
    k_fill<<<(N_EDGES + 255) / 256, 256>>>(ei);

    k_gemm<0><<<GB, 256, SMEM>>>(x, w1);
    k_aggregate<0><<<AB, 256>>>(b1, batch);
    k_gemm<1><<<GB, 256, SMEM>>>(x, w2);
    k_aggregate<0><<<AB, 256>>>(b2, batch);
    k_gemm<1><<<GB, 256, SMEM>>>(x, w3);
    k_aggregate<1><<<AB, 256>>>(b3, batch);   // fused mean-pool accumulation

    k_final<<<N_GRAPHS, 32>>>(lw, lb, out);
}